// round 9
// baseline (speedup 1.0000x reference)
#include <cuda_runtime.h>
#include <cstdint>

#define BATCH 8
#define NPTS  32768
#define NG    256
#define NC    64
#define KCAP  2048

__device__ float4 g_pbb[BATCH * NPTS];     // x,y,z,|p|^2(square-then-add)
__device__ int    g_fps[BATCH * NG];
__device__ float  g_code[BATCH * 256];
__device__ float  g_cdot[BATCH * 256];
__device__ float  g_rec[BATCH * NG * 3];
__device__ int    g_knn[BATCH * NG * NC];

// ---------------- K0: SoA prep + zero code ----------------
__global__ void k0_prep(const float* __restrict__ pts) {
    int i = blockIdx.x * 256 + threadIdx.x;
    float x = pts[i * 3], y = pts[i * 3 + 1], z = pts[i * 3 + 2];
    float bb = __fadd_rn(__fadd_rn(__fmul_rn(x, x), __fmul_rn(y, y)), __fmul_rn(z, z));
    g_pbb[i] = make_float4(x, y, z, bb);
    if (i < BATCH * 256) g_code[i] = 0.0f;
}

// ---------------- K1: FPS, one CTA per batch, points in registers ----------------
__global__ void __launch_bounds__(1024, 1) k1_fps() {
    __shared__ float s_wv[32];
    __shared__ int   s_wi[32];
    __shared__ int   s_win;
    __shared__ float s_sx, s_sy, s_sz;
    int b = blockIdx.x, tid = threadIdx.x;
    const float4* __restrict__ pb = g_pbb + b * NPTS;
    float px[32], py[32], pz[32], dist[32];
#pragma unroll
    for (int j = 0; j < 32; j++) {
        float4 q = pb[tid + j * 1024];
        px[j] = q.x; py[j] = q.y; pz[j] = q.z; dist[j] = 1e10f;
    }
    float4 q0 = pb[0];
    float sx = q0.x, sy = q0.y, sz = q0.z;
    int cur = 0;
    for (int it = 0; it < NG; it++) {
        if (tid == 0) g_fps[b * NG + it] = cur;
        float bv = -1.0f; int bi = 0;
#pragma unroll
        for (int j = 0; j < 32; j++) {
            float dx = __fsub_rn(px[j], sx), dy = __fsub_rn(py[j], sy), dz = __fsub_rn(pz[j], sz);
            float dd = __fadd_rn(__fadd_rn(__fmul_rn(dx, dx), __fmul_rn(dy, dy)), __fmul_rn(dz, dz));
            float nd = fminf(dist[j], dd);
            dist[j] = nd;
            if (nd > bv) { bv = nd; bi = tid + j * 1024; }
        }
#pragma unroll
        for (int off = 16; off; off >>= 1) {
            float ov = __shfl_down_sync(~0u, bv, off);
            int   oi = __shfl_down_sync(~0u, bi, off);
            if (ov > bv || (ov == bv && oi < bi)) { bv = ov; bi = oi; }
        }
        if ((tid & 31) == 0) { s_wv[tid >> 5] = bv; s_wi[tid >> 5] = bi; }
        __syncthreads();
        if (tid < 32) {
            bv = s_wv[tid]; bi = s_wi[tid];
#pragma unroll
            for (int off = 16; off; off >>= 1) {
                float ov = __shfl_down_sync(~0u, bv, off);
                int   oi = __shfl_down_sync(~0u, bi, off);
                if (ov > bv || (ov == bv && oi < bi)) { bv = ov; bi = oi; }
            }
            if (tid == 0) s_win = bi;
        }
        __syncthreads();
        int w = s_win;
        if ((w & 1023) == tid) { int j = w >> 10; s_sx = px[j]; s_sy = py[j]; s_sz = pz[j]; }
        __syncthreads();
        cur = w; sx = s_sx; sy = s_sy; sz = s_sz;
    }
}

// ---------------- K2: g2sd encoder + maxpool ----------------
__global__ void __launch_bounds__(128) k2_genc(const float* __restrict__ w1, const float* __restrict__ b1,
                                               const float* __restrict__ w2, const float* __restrict__ b2) {
    __shared__ float h1[128];
    int bg = blockIdx.x, b = bg >> 8, j = threadIdx.x;
    int pi = g_fps[bg];
    float4 q = g_pbb[b * NPTS + pi];
    float a = __fmaf_rn(q.z, w1[256 + j], __fmaf_rn(q.y, w1[128 + j], __fmul_rn(q.x, w1[j])));
    h1[j] = fmaxf(__fadd_rn(a, b1[j]), 0.0f);
    __syncthreads();
#pragma unroll
    for (int t = 0; t < 2; t++) {
        int ch = j + t * 128;
        float s = 0.0f;
        for (int k = 0; k < 128; k++) s = __fmaf_rn(h1[k], w2[k * 256 + ch], s);
        float h2 = fmaxf(__fadd_rn(s, b2[ch]), 0.0f);
        atomicMax((int*)&g_code[b * 256 + ch], __float_as_int(h2));
    }
}

// ---------------- K3a: per-batch code @ gd_w1[2:,:] ----------------
__global__ void __launch_bounds__(256) k3a(const float* __restrict__ w1) {
    __shared__ float cs[256];
    int b = blockIdx.x, j = threadIdx.x;
    cs[j] = g_code[b * 256 + j];
    __syncthreads();
    float s = 0.0f;
    for (int k = 0; k < 256; k++) s = __fmaf_rn(cs[k], w1[(2 + k) * 256 + j], s);
    g_cdot[b * 256 + j] = s;
}

// ---------------- K3b: g2sd folding decoder -> rec_g ----------------
__global__ void __launch_bounds__(256) k3b(const float* __restrict__ w1, const float* __restrict__ b1,
                                           const float* __restrict__ w2, const float* __restrict__ b2) {
    __shared__ float h[256];
    int bg = blockIdx.x, b = bg >> 8, g = bg & 255, j = threadIdx.x;
    float gx = __fmul_rn((float)(g & 15) + 0.5f, 0.0625f);
    float gy = __fmul_rn((float)(g >> 4) + 0.5f, 0.0625f);
    float a = __fmaf_rn(gy, w1[256 + j], __fmul_rn(gx, w1[j]));
    a = __fadd_rn(a, g_cdot[b * 256 + j]);
    h[j] = fmaxf(__fadd_rn(a, b1[j]), 0.0f);
    __syncthreads();
    if (j < 3) {
        float s = 0.0f;
        for (int k = 0; k < 256; k++) s = __fmaf_rn(h[k], w2[k * 3 + j], s);
        g_rec[bg * 3 + j] = __fadd_rn(s, b2[j]);
    }
}

// ---------------- K4: exact 64-NN via threshold stream + bitonic compact ----------------
__global__ void __launch_bounds__(256) k4_knn() {
    __shared__ unsigned long long buf[KCAP];
    __shared__ int cnt, s_flag;
    __shared__ unsigned long long thr_s;
    int bg = blockIdx.x, b = bg >> 8, tid = threadIdx.x;
    float ax = g_rec[bg * 3], ay = g_rec[bg * 3 + 1], az = g_rec[bg * 3 + 2];
    float aa = __fadd_rn(__fadd_rn(__fmul_rn(ax, ax), __fmul_rn(ay, ay)), __fmul_rn(az, az));
    if (tid == 0) { cnt = 0; thr_s = ~0ULL; }
    __syncthreads();
    const float4* __restrict__ pb = g_pbb + b * NPTS;
    unsigned long long thr = ~0ULL;

    auto compact = [&]() {
        int c = cnt;
        for (int t = tid; t < KCAP; t += 256) if (t >= c) buf[t] = ~0ULL;
        __syncthreads();
        for (int k = 2; k <= KCAP; k <<= 1)
            for (int j = k >> 1; j > 0; j >>= 1) {
                for (int t = tid; t < KCAP; t += 256) {
                    int x = t ^ j;
                    if (x > t) {
                        unsigned long long A = buf[t], Bv = buf[x];
                        bool up = ((t & k) == 0);
                        if (up ? (A > Bv) : (A < Bv)) { buf[t] = Bv; buf[x] = A; }
                    }
                }
                __syncthreads();
            }
        if (tid == 0) { cnt = NC; thr_s = buf[NC - 1]; }
        __syncthreads();
    };

    for (int base = 0; base < NPTS; base += 1024) {
#pragma unroll
        for (int i = 0; i < 4; i++) {
            int p = base + tid + i * 256;
            float4 q = pb[p];
            float ab = __fmaf_rn(az, q.z, __fmaf_rn(ay, q.y, __fmul_rn(ax, q.x)));
            float dd = __fsub_rn(__fadd_rn(aa, q.w), __fmul_rn(2.0f, ab));
            unsigned int kb = __float_as_uint(dd);
            kb = (kb & 0x80000000u) ? ~kb : (kb | 0x80000000u);
            unsigned long long key = ((unsigned long long)kb << 32) | (unsigned int)p;
            if (key < thr) {
                int pos = atomicAdd(&cnt, 1);
                if (pos < KCAP) buf[pos] = key;
            }
        }
        __syncthreads();
        if (tid == 0) s_flag = (cnt > 960);
        __syncthreads();
        if (s_flag) { compact(); thr = thr_s; }
    }
    compact();
    if (tid < NC) g_knn[bg * NC + tid] = (int)(unsigned int)(buf[tid] & 0xffffffffu);
}

// ---------------- K5: normalize + s2pf + rescale + resample + assemble ----------------
__global__ void __launch_bounds__(128) k5_patch(const float* __restrict__ sew1, const float* __restrict__ seb1,
                                                const float* __restrict__ sdw1, const float* __restrict__ sdb1,
                                                const float* __restrict__ sdw2, const float* __restrict__ sdb2,
                                                float* __restrict__ out) {
    __shared__ float px[NC], py[NC], pz[NC];
    __shared__ float nx[NC], ny[NC], nz[NC], nrm[NC];
    __shared__ float code[128];
    __shared__ float h2s[NC * 129];
    __shared__ float cen[3];
    __shared__ float ssc;
    __shared__ float pe[NC * 2];
    __shared__ float mnmx[4];
    __shared__ float ebd[NC * 2];
    int bg = blockIdx.x, b = bg >> 8, g = bg & 255, tid = threadIdx.x;

    if (tid < NC) {
        int pi = g_knn[bg * NC + tid];
        float4 q = g_pbb[b * NPTS + pi];
        px[tid] = q.x; py[tid] = q.y; pz[tid] = q.z;
    }
    __syncthreads();
    if (tid < 3) {
        const float* a = (tid == 0) ? px : ((tid == 1) ? py : pz);
        float s = 0.0f;
        for (int i = 0; i < NC; i++) s = __fadd_rn(s, a[i]);
        cen[tid] = __fdiv_rn(s, 64.0f);
    }
    __syncthreads();
    if (tid < NC) {
        float dx = __fsub_rn(px[tid], cen[0]);
        float dy = __fsub_rn(py[tid], cen[1]);
        float dz = __fsub_rn(pz[tid], cen[2]);
        nx[tid] = dx; ny[tid] = dy; nz[tid] = dz;
        nrm[tid] = __fsqrt_rn(__fadd_rn(__fadd_rn(__fmul_rn(dx, dx), __fmul_rn(dy, dy)), __fmul_rn(dz, dz)));
    }
    __syncthreads();
    if (tid == 0) {
        float m = nrm[0];
        for (int i = 1; i < NC; i++) m = fmaxf(m, nrm[i]);
        ssc = __fadd_rn(m, 1e-8f);
    }
    __syncthreads();
    if (tid < NC) {
        nx[tid] = __fdiv_rn(nx[tid], ssc);
        ny[tid] = __fdiv_rn(ny[tid], ssc);
        nz[tid] = __fdiv_rn(nz[tid], ssc);
    }
    __syncthreads();
    {   // s2pf encoder + maxpool
        int j = tid;
        float w0 = sew1[j], w1 = sew1[128 + j], w2 = sew1[256 + j], bb = seb1[j];
        float mx = 0.0f;
        for (int p = 0; p < NC; p++) {
            float a = __fmaf_rn(nz[p], w2, __fmaf_rn(ny[p], w1, __fmul_rn(nx[p], w0)));
            float hh = fmaxf(__fadd_rn(a, bb), 0.0f);
            mx = (p == 0) ? hh : fmaxf(mx, hh);
        }
        code[j] = mx;
    }
    __syncthreads();
    {   // h2 with hoisted code-dot
        int j = tid;
        float base = 0.0f;
        for (int k = 0; k < 128; k++) base = __fmaf_rn(code[k], sdw1[(3 + k) * 128 + j], base);
        float w0 = sdw1[j], w1 = sdw1[128 + j], w2 = sdw1[256 + j], bb = sdb1[j];
        for (int p = 0; p < NC; p++) {
            float a = __fadd_rn(__fmaf_rn(nz[p], w2, __fmaf_rn(ny[p], w1, __fmul_rn(nx[p], w0))), base);
            h2s[p * 129 + j] = fmaxf(__fadd_rn(a, bb), 0.0f);
        }
    }
    __syncthreads();
    {   // pe = h2 @ sd_w2 + b
        int p = tid & 63, c = tid >> 6;
        float s = 0.0f;
        for (int j = 0; j < 128; j++) s = __fmaf_rn(h2s[p * 129 + j], sdw2[j * 2 + c], s);
        pe[p * 2 + c] = __fadd_rn(s, sdb2[c]);
    }
    __syncthreads();
    if (tid < 2) {
        float mn = pe[tid], mx = pe[tid];
        for (int p = 1; p < NC; p++) { float v = pe[p * 2 + tid]; mn = fminf(mn, v); mx = fmaxf(mx, v); }
        mnmx[tid] = mn; mnmx[2 + tid] = mx;
    }
    __syncthreads();
    {
        int p = tid & 63, c = tid >> 6;
        const float HIL = (float)((1.0 - 1e-6) - 1e-6);
        float t = __fdiv_rn(__fsub_rn(pe[p * 2 + c], mnmx[c]),
                            __fadd_rn(__fsub_rn(mnmx[2 + c], mnmx[c]), 1e-8f));
        ebd[p * 2 + c] = __fadd_rn(__fmul_rn(t, HIL), 1e-6f);
    }
    __syncthreads();
    if (tid < 16) {   // per-cell nearest + assemble
        int k = tid;
        float gx = __fmul_rn((float)(k & 3) + 0.5f, 0.25f);
        float gy = __fmul_rn((float)(k >> 2) + 0.5f, 0.25f);
        float bd = 1e30f; int bi = 0;
        for (int p = 0; p < NC; p++) {
            float dx = __fsub_rn(gx, ebd[p * 2]);
            float dy = __fsub_rn(gy, ebd[p * 2 + 1]);
            float d2 = __fadd_rn(__fmul_rn(dx, dx), __fmul_rn(dy, dy));
            if (d2 < bd) { bd = d2; bi = p; }
        }
        int m = ((g >> 4) * 4 + (k >> 2)) * 64 + (g & 15) * 4 + (k & 3);
        float* o = out + ((long)b * 4096 + m) * 3;
        o[0] = px[bi]; o[1] = py[bi]; o[2] = pz[bi];
    }
}

extern "C" void kernel_launch(void* const* d_in, const int* in_sizes, int n_in,
                              void* d_out, int out_size) {
    const float* pts  = (const float*)d_in[0];
    const float* gew1 = (const float*)d_in[1];
    const float* geb1 = (const float*)d_in[2];
    const float* gew2 = (const float*)d_in[3];
    const float* geb2 = (const float*)d_in[4];
    const float* gdw1 = (const float*)d_in[5];
    const float* gdb1 = (const float*)d_in[6];
    const float* gdw2 = (const float*)d_in[7];
    const float* gdb2 = (const float*)d_in[8];
    const float* sew1 = (const float*)d_in[9];
    const float* seb1 = (const float*)d_in[10];
    const float* sdw1 = (const float*)d_in[11];
    const float* sdb1 = (const float*)d_in[12];
    const float* sdw2 = (const float*)d_in[13];
    const float* sdb2 = (const float*)d_in[14];
    float* out = (float*)d_out;

    k0_prep<<<BATCH * NPTS / 256, 256>>>(pts);
    k1_fps<<<BATCH, 1024>>>();
    k2_genc<<<BATCH * NG, 128>>>(gew1, geb1, gew2, geb2);
    k3a<<<BATCH, 256>>>(gdw1);
    k3b<<<BATCH * NG, 256>>>(gdw1, gdb1, gdw2, gdb2);
    k4_knn<<<BATCH * NG, 256>>>();
    k5_patch<<<BATCH * NG, 128>>>(sew1, seb1, sdw1, sdb1, sdw2, sdb2, out);
}

// round 10
// speedup vs baseline: 2.8009x; 2.8009x over previous
#include <cuda_runtime.h>
#include <cstdint>

#define BATCH 8
#define NPTS  32768
#define NG    256
#define NC    64
#define KCAP  2048

__device__ float4 g_pbb[BATCH * NPTS];     // x,y,z,|p|^2 (square-then-add)
__device__ int    g_fps[BATCH * NG];
__device__ float  g_code[BATCH * 256];
__device__ float  g_cdot[BATCH * 256];
__device__ float  g_rec[BATCH * NG * 3];
__device__ int    g_knn[BATCH * NG * NC];

// ---------------- K0: SoA prep + zero code ----------------
__global__ void k0_prep(const float* __restrict__ pts) {
    int i = blockIdx.x * 256 + threadIdx.x;
    float x = pts[i * 3], y = pts[i * 3 + 1], z = pts[i * 3 + 2];
    float bb = __fadd_rn(__fadd_rn(__fmul_rn(x, x), __fmul_rn(y, y)), __fmul_rn(z, z));
    g_pbb[i] = make_float4(x, y, z, bb);
    if (i < BATCH * 256) g_code[i] = 0.0f;
}

// ---------------- K1: FPS — 8-CTA cluster per batch, points in registers ----------------
// 512 thr/CTA * 8 CTAs = 4096 threads, 8 pts/thread (32 array regs, no spill).
// One cluster barrier per iteration; per-CTA winner records exchanged via DSMEM,
// double-buffered by iteration parity (race-free without a second barrier).
__global__ void __cluster_dims__(8, 1, 1) __launch_bounds__(512, 1) k1_fps() {
    __shared__ float s_wv[16];
    __shared__ int   s_wi[16];
    __shared__ float s_wx[16], s_wy[16], s_wz[16];
    __shared__ __align__(16) unsigned int s_exch[2][8 * 8];   // [parity][slot*8 words]
    __shared__ float s_sx, s_sy, s_sz;
    __shared__ int   s_cur;

    int rank = blockIdx.x & 7;
    int b    = blockIdx.x >> 3;
    int tid  = threadIdx.x;
    int base = rank * 4096;

    const float4* __restrict__ pb = g_pbb + b * NPTS;

    float px[8], py[8], pz[8], dist[8];
#pragma unroll
    for (int j = 0; j < 8; j++) {
        float4 q = pb[base + tid + j * 512];
        px[j] = q.x; py[j] = q.y; pz[j] = q.z; dist[j] = 1e10f;
    }
    float4 q0 = pb[0];
    float sx = q0.x, sy = q0.y, sz = q0.z;
    int cur = 0;

    unsigned int sb0 = (unsigned int)__cvta_generic_to_shared(&s_exch[0][0]);
    unsigned int sb1 = (unsigned int)__cvta_generic_to_shared(&s_exch[1][0]);

    for (int it = 0; it < NG; it++) {
        if (rank == 0 && tid == 0) g_fps[b * NG + it] = cur;

        float bv = -1.0f, bx = 0.f, by = 0.f, bz = 0.f;
        int bi = 0x7fffffff;
#pragma unroll
        for (int j = 0; j < 8; j++) {
            float dx = __fsub_rn(px[j], sx), dy = __fsub_rn(py[j], sy), dz = __fsub_rn(pz[j], sz);
            float dd = __fadd_rn(__fadd_rn(__fmul_rn(dx, dx), __fmul_rn(dy, dy)), __fmul_rn(dz, dz));
            float nd = fminf(dist[j], dd);
            dist[j] = nd;
            if (nd > bv) { bv = nd; bi = base + tid + j * 512; bx = px[j]; by = py[j]; bz = pz[j]; }
        }
#pragma unroll
        for (int off = 16; off; off >>= 1) {
            float ov = __shfl_down_sync(~0u, bv, off);
            int   oi = __shfl_down_sync(~0u, bi, off);
            float ox = __shfl_down_sync(~0u, bx, off);
            float oy = __shfl_down_sync(~0u, by, off);
            float oz = __shfl_down_sync(~0u, bz, off);
            if (ov > bv || (ov == bv && oi < bi)) { bv = ov; bi = oi; bx = ox; by = oy; bz = oz; }
        }
        if ((tid & 31) == 0) {
            int w = tid >> 5;
            s_wv[w] = bv; s_wi[w] = bi; s_wx[w] = bx; s_wy[w] = by; s_wz[w] = bz;
        }
        __syncthreads();
        if (tid < 32) {
            bool ok = tid < 16;
            bv = ok ? s_wv[tid] : -1.0f;
            bi = ok ? s_wi[tid] : 0x7fffffff;
            bx = ok ? s_wx[tid] : 0.f;
            by = ok ? s_wy[tid] : 0.f;
            bz = ok ? s_wz[tid] : 0.f;
#pragma unroll
            for (int off = 8; off; off >>= 1) {
                float ov = __shfl_down_sync(~0u, bv, off);
                int   oi = __shfl_down_sync(~0u, bi, off);
                float ox = __shfl_down_sync(~0u, bx, off);
                float oy = __shfl_down_sync(~0u, by, off);
                float oz = __shfl_down_sync(~0u, bz, off);
                if (ov > bv || (ov == bv && oi < bi)) { bv = ov; bi = oi; bx = ox; by = oy; bz = oz; }
            }
            if (tid == 0) {
                unsigned int sb = (it & 1) ? sb1 : sb0;
                unsigned int v0 = __float_as_uint(bv);
                unsigned int v1 = (unsigned int)bi;
                unsigned int v2 = __float_as_uint(bx);
                unsigned int v3 = __float_as_uint(by);
                unsigned int v4 = __float_as_uint(bz);
#pragma unroll
                for (int r = 0; r < 8; r++) {
                    unsigned int ra;
                    asm volatile("mapa.shared::cluster.u32 %0, %1, %2;"
                                 : "=r"(ra) : "r"(sb + rank * 32), "r"(r));
                    asm volatile("st.shared::cluster.v4.b32 [%0], {%1,%2,%3,%4};"
                                 :: "r"(ra), "r"(v0), "r"(v1), "r"(v2), "r"(v3) : "memory");
                    asm volatile("st.shared::cluster.b32 [%0+16], %1;"
                                 :: "r"(ra), "r"(v4) : "memory");
                }
            }
        }
        asm volatile("barrier.cluster.arrive.aligned;" ::: "memory");
        asm volatile("barrier.cluster.wait.aligned;" ::: "memory");

        if (tid == 0) {
            const unsigned int* e = s_exch[it & 1];
            float wv = -1.0f; int wi = 0x7fffffff;
            float nsx = 0.f, nsy = 0.f, nsz = 0.f;
#pragma unroll
            for (int r = 0; r < 8; r++) {
                float v  = __uint_as_float(e[r * 8 + 0]);
                int   i  = (int)e[r * 8 + 1];
                if (v > wv || (v == wv && i < wi)) {
                    wv = v; wi = i;
                    nsx = __uint_as_float(e[r * 8 + 2]);
                    nsy = __uint_as_float(e[r * 8 + 3]);
                    nsz = __uint_as_float(e[r * 8 + 4]);
                }
            }
            s_cur = wi; s_sx = nsx; s_sy = nsy; s_sz = nsz;
        }
        __syncthreads();
        cur = s_cur; sx = s_sx; sy = s_sy; sz = s_sz;
    }
}

// ---------------- K2: g2sd encoder + maxpool ----------------
__global__ void __launch_bounds__(128) k2_genc(const float* __restrict__ w1, const float* __restrict__ b1,
                                               const float* __restrict__ w2, const float* __restrict__ b2) {
    __shared__ float h1[128];
    int bg = blockIdx.x, b = bg >> 8, j = threadIdx.x;
    int pi = g_fps[bg];
    float4 q = g_pbb[b * NPTS + pi];
    float a = __fmaf_rn(q.z, w1[256 + j], __fmaf_rn(q.y, w1[128 + j], __fmul_rn(q.x, w1[j])));
    h1[j] = fmaxf(__fadd_rn(a, b1[j]), 0.0f);
    __syncthreads();
#pragma unroll
    for (int t = 0; t < 2; t++) {
        int ch = j + t * 128;
        float s = 0.0f;
        for (int k = 0; k < 128; k++) s = __fmaf_rn(h1[k], w2[k * 256 + ch], s);
        float h2 = fmaxf(__fadd_rn(s, b2[ch]), 0.0f);
        atomicMax((int*)&g_code[b * 256 + ch], __float_as_int(h2));
    }
}

// ---------------- K3a: per-batch code @ gd_w1[2:,:] ----------------
__global__ void __launch_bounds__(256) k3a(const float* __restrict__ w1) {
    __shared__ float cs[256];
    int b = blockIdx.x, j = threadIdx.x;
    cs[j] = g_code[b * 256 + j];
    __syncthreads();
    float s = 0.0f;
    for (int k = 0; k < 256; k++) s = __fmaf_rn(cs[k], w1[(2 + k) * 256 + j], s);
    g_cdot[b * 256 + j] = s;
}

// ---------------- K3b: g2sd folding decoder -> rec_g ----------------
__global__ void __launch_bounds__(256) k3b(const float* __restrict__ w1, const float* __restrict__ b1,
                                           const float* __restrict__ w2, const float* __restrict__ b2) {
    __shared__ float h[256];
    int bg = blockIdx.x, b = bg >> 8, g = bg & 255, j = threadIdx.x;
    float gx = __fmul_rn((float)(g & 15) + 0.5f, 0.0625f);
    float gy = __fmul_rn((float)(g >> 4) + 0.5f, 0.0625f);
    float a = __fmaf_rn(gy, w1[256 + j], __fmul_rn(gx, w1[j]));
    a = __fadd_rn(a, g_cdot[b * 256 + j]);
    h[j] = fmaxf(__fadd_rn(a, b1[j]), 0.0f);
    __syncthreads();
    if (j < 3) {
        float s = 0.0f;
        for (int k = 0; k < 256; k++) s = __fmaf_rn(h[k], w2[k * 3 + j], s);
        g_rec[bg * 3 + j] = __fadd_rn(s, b2[j]);
    }
}

// ---------------- K4: exact 64-NN, threshold stream + pow2-sized bitonic compact ----------------
__global__ void __launch_bounds__(256) k4_knn() {
    __shared__ unsigned long long buf[KCAP];
    __shared__ int cnt, s_flag;
    __shared__ unsigned long long thr_s;
    int bg = blockIdx.x, b = bg >> 8, tid = threadIdx.x;
    float ax = g_rec[bg * 3], ay = g_rec[bg * 3 + 1], az = g_rec[bg * 3 + 2];
    float aa = __fadd_rn(__fadd_rn(__fmul_rn(ax, ax), __fmul_rn(ay, ay)), __fmul_rn(az, az));
    if (tid == 0) { cnt = 0; thr_s = ~0ULL; }
    __syncthreads();
    const float4* __restrict__ pb = g_pbb + b * NPTS;
    unsigned long long thr = ~0ULL;

    auto compact = [&]() {
        int c = cnt;                       // uniform (post-sync)
        int S = 64; while (S < c) S <<= 1; // pow2 >= c, >= 64  (c <= 1984 < KCAP)
        for (int t = tid; t < S; t += 256) if (t >= c) buf[t] = ~0ULL;
        __syncthreads();
        for (int k = 2; k <= S; k <<= 1)
            for (int j = k >> 1; j > 0; j >>= 1) {
                for (int t = tid; t < S; t += 256) {
                    int x = t ^ j;
                    if (x > t) {
                        unsigned long long A = buf[t], Bv = buf[x];
                        bool up = ((t & k) == 0);
                        if (up ? (A > Bv) : (A < Bv)) { buf[t] = Bv; buf[x] = A; }
                    }
                }
                __syncthreads();
            }
        if (tid == 0) { cnt = NC; thr_s = buf[NC - 1]; }
        __syncthreads();
    };

    for (int base = 0; base < NPTS; base += 1024) {
#pragma unroll
        for (int i = 0; i < 4; i++) {
            int p = base + tid + i * 256;
            float4 q = pb[p];
            float ab = __fmaf_rn(az, q.z, __fmaf_rn(ay, q.y, __fmul_rn(ax, q.x)));
            float dd = __fsub_rn(__fadd_rn(aa, q.w), __fmul_rn(2.0f, ab));
            unsigned int kb = __float_as_uint(dd);
            kb = (kb & 0x80000000u) ? ~kb : (kb | 0x80000000u);
            unsigned long long key = ((unsigned long long)kb << 32) | (unsigned int)p;
            if (key < thr) {
                int pos = atomicAdd(&cnt, 1);
                if (pos < KCAP) buf[pos] = key;
            }
        }
        __syncthreads();
        if (tid == 0) s_flag = (cnt > 960);
        __syncthreads();
        if (s_flag) { compact(); thr = thr_s; }
    }
    compact();
    if (tid < NC) g_knn[bg * NC + tid] = (int)(unsigned int)(buf[tid] & 0xffffffffu);
}

// ---------------- K5: normalize + s2pf + rescale + resample + assemble ----------------
__global__ void __launch_bounds__(128) k5_patch(const float* __restrict__ sew1, const float* __restrict__ seb1,
                                                const float* __restrict__ sdw1, const float* __restrict__ sdb1,
                                                const float* __restrict__ sdw2, const float* __restrict__ sdb2,
                                                float* __restrict__ out) {
    __shared__ float px[NC], py[NC], pz[NC];
    __shared__ float nx[NC], ny[NC], nz[NC], nrm[NC];
    __shared__ float code[128];
    __shared__ float h2s[NC * 129];
    __shared__ float cen[3];
    __shared__ float ssc;
    __shared__ float pe[NC * 2];
    __shared__ float mnmx[4];
    __shared__ float ebd[NC * 2];
    int bg = blockIdx.x, b = bg >> 8, g = bg & 255, tid = threadIdx.x;

    if (tid < NC) {
        int pi = g_knn[bg * NC + tid];
        float4 q = g_pbb[b * NPTS + pi];
        px[tid] = q.x; py[tid] = q.y; pz[tid] = q.z;
    }
    __syncthreads();
    if (tid < 3) {
        const float* a = (tid == 0) ? px : ((tid == 1) ? py : pz);
        float s = 0.0f;
        for (int i = 0; i < NC; i++) s = __fadd_rn(s, a[i]);
        cen[tid] = __fdiv_rn(s, 64.0f);
    }
    __syncthreads();
    if (tid < NC) {
        float dx = __fsub_rn(px[tid], cen[0]);
        float dy = __fsub_rn(py[tid], cen[1]);
        float dz = __fsub_rn(pz[tid], cen[2]);
        nx[tid] = dx; ny[tid] = dy; nz[tid] = dz;
        nrm[tid] = __fsqrt_rn(__fadd_rn(__fadd_rn(__fmul_rn(dx, dx), __fmul_rn(dy, dy)), __fmul_rn(dz, dz)));
    }
    __syncthreads();
    if (tid == 0) {
        float m = nrm[0];
        for (int i = 1; i < NC; i++) m = fmaxf(m, nrm[i]);
        ssc = __fadd_rn(m, 1e-8f);
    }
    __syncthreads();
    if (tid < NC) {
        nx[tid] = __fdiv_rn(nx[tid], ssc);
        ny[tid] = __fdiv_rn(ny[tid], ssc);
        nz[tid] = __fdiv_rn(nz[tid], ssc);
    }
    __syncthreads();
    {   // s2pf encoder + maxpool
        int j = tid;
        float w0 = sew1[j], w1 = sew1[128 + j], w2 = sew1[256 + j], bb = seb1[j];
        float mx = 0.0f;
        for (int p = 0; p < NC; p++) {
            float a = __fmaf_rn(nz[p], w2, __fmaf_rn(ny[p], w1, __fmul_rn(nx[p], w0)));
            float hh = fmaxf(__fadd_rn(a, bb), 0.0f);
            mx = (p == 0) ? hh : fmaxf(mx, hh);
        }
        code[j] = mx;
    }
    __syncthreads();
    {   // h2 with hoisted code-dot
        int j = tid;
        float base = 0.0f;
        for (int k = 0; k < 128; k++) base = __fmaf_rn(code[k], sdw1[(3 + k) * 128 + j], base);
        float w0 = sdw1[j], w1 = sdw1[128 + j], w2 = sdw1[256 + j], bb = sdb1[j];
        for (int p = 0; p < NC; p++) {
            float a = __fadd_rn(__fmaf_rn(nz[p], w2, __fmaf_rn(ny[p], w1, __fmul_rn(nx[p], w0))), base);
            h2s[p * 129 + j] = fmaxf(__fadd_rn(a, bb), 0.0f);
        }
    }
    __syncthreads();
    {   // pe = h2 @ sd_w2 + b
        int p = tid & 63, c = tid >> 6;
        float s = 0.0f;
        for (int j = 0; j < 128; j++) s = __fmaf_rn(h2s[p * 129 + j], sdw2[j * 2 + c], s);
        pe[p * 2 + c] = __fadd_rn(s, sdb2[c]);
    }
    __syncthreads();
    if (tid < 2) {
        float mn = pe[tid], mx = pe[tid];
        for (int p = 1; p < NC; p++) { float v = pe[p * 2 + tid]; mn = fminf(mn, v); mx = fmaxf(mx, v); }
        mnmx[tid] = mn; mnmx[2 + tid] = mx;
    }
    __syncthreads();
    {
        int p = tid & 63, c = tid >> 6;
        const float HIL = (float)((1.0 - 1e-6) - 1e-6);
        float t = __fdiv_rn(__fsub_rn(pe[p * 2 + c], mnmx[c]),
                            __fadd_rn(__fsub_rn(mnmx[2 + c], mnmx[c]), 1e-8f));
        ebd[p * 2 + c] = __fadd_rn(__fmul_rn(t, HIL), 1e-6f);
    }
    __syncthreads();
    if (tid < 16) {   // per-cell nearest + assemble
        int k = tid;
        float gx = __fmul_rn((float)(k & 3) + 0.5f, 0.25f);
        float gy = __fmul_rn((float)(k >> 2) + 0.5f, 0.25f);
        float bd = 1e30f; int bi = 0;
        for (int p = 0; p < NC; p++) {
            float dx = __fsub_rn(gx, ebd[p * 2]);
            float dy = __fsub_rn(gy, ebd[p * 2 + 1]);
            float d2 = __fadd_rn(__fmul_rn(dx, dx), __fmul_rn(dy, dy));
            if (d2 < bd) { bd = d2; bi = p; }
        }
        int m = ((g >> 4) * 4 + (k >> 2)) * 64 + (g & 15) * 4 + (k & 3);
        float* o = out + ((long)b * 4096 + m) * 3;
        o[0] = px[bi]; o[1] = py[bi]; o[2] = pz[bi];
    }
}

extern "C" void kernel_launch(void* const* d_in, const int* in_sizes, int n_in,
                              void* d_out, int out_size) {
    const float* pts  = (const float*)d_in[0];
    const float* gew1 = (const float*)d_in[1];
    const float* geb1 = (const float*)d_in[2];
    const float* gew2 = (const float*)d_in[3];
    const float* geb2 = (const float*)d_in[4];
    const float* gdw1 = (const float*)d_in[5];
    const float* gdb1 = (const float*)d_in[6];
    const float* gdw2 = (const float*)d_in[7];
    const float* gdb2 = (const float*)d_in[8];
    const float* sew1 = (const float*)d_in[9];
    const float* seb1 = (const float*)d_in[10];
    const float* sdw1 = (const float*)d_in[11];
    const float* sdb1 = (const float*)d_in[12];
    const float* sdw2 = (const float*)d_in[13];
    const float* sdb2 = (const float*)d_in[14];
    float* out = (float*)d_out;

    k0_prep<<<BATCH * NPTS / 256, 256>>>(pts);
    k1_fps<<<BATCH * 8, 512>>>();
    k2_genc<<<BATCH * NG, 128>>>(gew1, geb1, gew2, geb2);
    k3a<<<BATCH, 256>>>(gdw1);
    k3b<<<BATCH * NG, 256>>>(gdw1, gdb1, gdw2, gdb2);
    k4_knn<<<BATCH * NG, 256>>>();
    k5_patch<<<BATCH * NG, 128>>>(sew1, seb1, sdw1, sdb1, sdw2, sdb2, out);
}